// round 14
// baseline (speedup 1.0000x reference)
#include <cuda_runtime.h>
#include <cuda_bf16.h>
#include <cuda_fp16.h>
#include <math.h>
#include <stdint.h>

#define CH    64
#define DDIM  48
#define WDIM  128
#define HDIM  128
#define S_TOT (DDIM*WDIM*HDIM)   /* 786432 spatial positions */
#define SLAB  (WDIM*HDIM)        /* 16384 per (c,d) slab     */
#define NSLAB (CH*DDIM)          /* 3072 attention problems  */

#define QSCALE 0.594603557501360533f   /* 8^(-1/4) */

/* q/k fragment-ordered uint4 {hi,lo,hi+4,lo+4}; v fp16x2 pairs; O fp16 */
__device__ uint4          g_q4[CH * S_TOT / 4];
__device__ uint4          g_k4[CH * S_TOT / 4];
__device__ uint32_t       g_vf[CH * S_TOT / 2];
__device__ unsigned short g_of[CH * S_TOT];

/* ---------------- mma.sync helpers (legal in compute_103 PTX) ---------- */
__device__ __forceinline__ void mma_bf16(float c[4],
                                         uint32_t a0, uint32_t a1, uint32_t a2, uint32_t a3,
                                         uint32_t b0, uint32_t b1) {
    asm volatile(
        "mma.sync.aligned.m16n8k16.row.col.f32.bf16.bf16.f32 "
        "{%0,%1,%2,%3}, {%4,%5,%6,%7}, {%8,%9}, {%0,%1,%2,%3};"
        : "+f"(c[0]), "+f"(c[1]), "+f"(c[2]), "+f"(c[3])
        : "r"(a0), "r"(a1), "r"(a2), "r"(a3), "r"(b0), "r"(b1));
}
__device__ __forceinline__ void mma_f16(float c[4],
                                        uint32_t a0, uint32_t a1, uint32_t a2, uint32_t a3,
                                        uint32_t b0, uint32_t b1) {
    asm volatile(
        "mma.sync.aligned.m16n8k16.row.col.f32.f16.f16.f32 "
        "{%0,%1,%2,%3}, {%4,%5,%6,%7}, {%8,%9}, {%0,%1,%2,%3};"
        : "+f"(c[0]), "+f"(c[1]), "+f"(c[2]), "+f"(c[3])
        : "r"(a0), "r"(a1), "r"(a2), "r"(a3), "r"(b0), "r"(b1));
}
/* 2-term bf16 Dekker split of a pair (x->low half, y->high half) */
__device__ __forceinline__ void bf16_split2(float x, float y, uint32_t& h, uint32_t& l) {
    __nv_bfloat162 hb = __floats2bfloat162_rn(x, y);
    float rx = x - __bfloat162float(hb.x);
    float ry = y - __bfloat162float(hb.y);
    __nv_bfloat162 lb = __floats2bfloat162_rn(rx, ry);
    h = *(uint32_t*)&hb;
    l = *(uint32_t*)&lb;
}
/* 2-term fp16 Dekker split of a pair */
__device__ __forceinline__ void f16_split2(float x, float y, uint32_t& h, uint32_t& l) {
    __half hx = __float2half_rn(x), hy = __float2half_rn(y);
    __half lx = __float2half_rn(x - __half2float(hx));
    __half ly = __float2half_rn(y - __half2float(hy));
    __half2 hh = __halves2half2(hx, hy);
    __half2 ll = __halves2half2(lx, ly);
    h = *(uint32_t*)&hh;
    l = *(uint32_t*)&ll;
}
__device__ __forceinline__ uint32_t f16pack(float x, float y) {
    __half2 h = __floats2half2_rn(x, y);
    return *(uint32_t*)&h;
}

/* ------------------------------------------------------------------ */
/* Phase 1: fused QKV projection, bf16 m16n8k16, 3-term split.         */
/* ------------------------------------------------------------------ */
#define XP2 268                           /* uint2 pitch (bank-checked) */
#define P1_SMEM (32 * XP2 * 8)            /* 68608 B                    */

__global__ void __launch_bounds__(384, 2) qkv_kernel(
    const float* __restrict__ x,
    const float* __restrict__ wq, const float* __restrict__ bq,
    const float* __restrict__ wk, const float* __restrict__ bk,
    const float* __restrict__ wv, const float* __restrict__ bv)
{
    extern __shared__ uint2 xs[];          /* [32][268] {hi,lo} */

    const int tid  = threadIdx.x;
    const int lane = tid & 31;
    const int wrp  = tid >> 5;
    const int lg   = lane >> 2;
    const int la   = lane & 3;
    const int s0   = blockIdx.x * 256;
    const int d    = s0 / 16384;
    const int wb   = (s0 % 16384) / 128;

    const int p  = wrp >> 2;                 /* 0=q 1=k 2=v */
    const int c0 = (wrp & 3) * 16;
    const float* W = (p == 0) ? wq : (p == 1) ? wk : wv;
    const float* B = (p == 0) ? bq : (p == 1) ? bk : bv;

    uint32_t ah[16], al[16];
    #pragma unroll
    for (int kt = 0; kt < 4; kt++) {
        int kk = kt*16 + 2*la;
        float2 w0 = *(const float2*)&W[(c0 + lg    )*64 + kk    ];
        float2 w1 = *(const float2*)&W[(c0 + lg + 8)*64 + kk    ];
        float2 w2 = *(const float2*)&W[(c0 + lg    )*64 + kk + 8];
        float2 w3 = *(const float2*)&W[(c0 + lg + 8)*64 + kk + 8];
        bf16_split2(w0.x, w0.y, ah[kt*4+0], al[kt*4+0]);
        bf16_split2(w1.x, w1.y, ah[kt*4+1], al[kt*4+1]);
        bf16_split2(w2.x, w2.y, ah[kt*4+2], al[kt*4+2]);
        bf16_split2(w3.x, w3.y, ah[kt*4+3], al[kt*4+3]);
    }
    const float b1 = B[c0 + lg];
    const float b2 = B[c0 + lg + 8];
    const float scale = (p == 0) ? QSCALE : 1.0f;
    uint4* g4 = (p == 0) ? g_q4 : g_k4;

    for (int i = tid; i < 32*64; i += 384) {
        int kp = i >> 6, q4 = i & 63;
        int col0 = q4 * 4;
        float4 a = *(const float4*)&x[(size_t)(2*kp  ) * S_TOT + s0 + col0];
        float4 b = *(const float4*)&x[(size_t)(2*kp+1) * S_TOT + s0 + col0];
        uint4 wh, wl;
        bf16_split2(a.x, b.x, wh.x, wl.x);
        bf16_split2(a.y, b.y, wh.y, wl.y);
        bf16_split2(a.z, b.z, wh.z, wl.z);
        bf16_split2(a.w, b.w, wh.w, wl.w);
        *(uint4*)&xs[kp*XP2 + col0    ] = make_uint4(wh.x, wl.x, wh.y, wl.y);
        *(uint4*)&xs[kp*XP2 + col0 + 2] = make_uint4(wh.z, wl.z, wh.w, wl.w);
    }
    __syncthreads();

    #pragma unroll 1
    for (int qt = 0; qt < 4; qt++) {
        float c[8][4];
        #pragma unroll
        for (int n = 0; n < 8; n++) {
            c[n][0] = b1; c[n][1] = b1; c[n][2] = b2; c[n][3] = b2;
        }

        #pragma unroll 1
        for (int kt = 0; kt < 4; kt++) {
            const int b0i = (8*kt + la)*XP2 + qt*64 + lg;
            const int b1i = b0i + 4*XP2;
            #pragma unroll
            for (int n = 0; n < 8; n++) {
                uint2 B0 = xs[b0i + n*8];
                uint2 B1 = xs[b1i + n*8];
                mma_bf16(c[n], ah[kt*4+0], ah[kt*4+1], ah[kt*4+2], ah[kt*4+3], B0.x, B1.x);
                mma_bf16(c[n], ah[kt*4+0], ah[kt*4+1], ah[kt*4+2], ah[kt*4+3], B0.y, B1.y);
                mma_bf16(c[n], al[kt*4+0], al[kt*4+1], al[kt*4+2], al[kt*4+3], B0.x, B1.x);
            }
        }

        if (p < 2) {
            const int w = wb + (qt >> 1);
            #pragma unroll
            for (int ne = 0; ne < 8; ne += 2) {
                const int kt_h = (qt & 1)*4 + (ne >> 1);
                const size_t fi = (size_t)d*4096 + kt_h*512 + w*4 + la;
                uint32_t h0, l0, h1, l1;
                bf16_split2(c[ne  ][0]*scale, c[ne  ][1]*scale, h0, l0);
                bf16_split2(c[ne+1][0]*scale, c[ne+1][1]*scale, h1, l1);
                g4[(size_t)(c0 + lg    )*(S_TOT/4) + fi] = make_uint4(h0, l0, h1, l1);
                bf16_split2(c[ne  ][2]*scale, c[ne  ][3]*scale, h0, l0);
                bf16_split2(c[ne+1][2]*scale, c[ne+1][3]*scale, h1, l1);
                g4[(size_t)(c0 + lg + 8)*(S_TOT/4) + fi] = make_uint4(h0, l0, h1, l1);
            }
        } else {
            #pragma unroll
            for (int n = 0; n < 8; n++) {
                const int scol = ((s0 + qt*64 + n*8) >> 1) + la;
                g_vf[(size_t)(c0 + lg    )*(S_TOT/2) + scol] = f16pack(c[n][0], c[n][1]);
                g_vf[(size_t)(c0 + lg + 8)*(S_TOT/2) + scol] = f16pack(c[n][2], c[n][3]);
            }
        }
    }
}

/* ------------------------------------------------------------------ */
/* Phase 2: attention. A stays in registers (S C-frag == AV A-frag);   */
/* no smem round-trip, no softmax->AV block barrier.                   */
/* ------------------------------------------------------------------ */
#define ATV_OFF 65536
#define AT_SMEM (65536 + 34816)

__global__ void __launch_bounds__(256, 2) attn_kernel()
{
    extern __shared__ char smc[];
    uint4*    Ksm = (uint4*)smc;                  /* [8][128][4] uint4  */
    uint32_t* Vp  = (uint32_t*)(smc + ATV_OFF);   /* [64][136] fp16x2   */

    const int tid  = threadIdx.x;
    const int lane = tid & 31;
    const int wrp  = tid >> 5;
    const int lg   = lane >> 2;
    const int la   = lane & 3;
    const size_t base = (size_t)blockIdx.x * SLAB;

    const uint4* Kg4 = g_k4 + (size_t)blockIdx.x * 4096;
    for (int i = tid; i < 4096; i += 256)
        Ksm[i] = Kg4[i];
    const uint4* Vf4 = (const uint4*)g_vf + (size_t)blockIdx.x * 2048;
    for (int i = tid; i < 1024; i += 256) {
        int kp = i >> 4, u = i & 15;
        uint4 e = Vf4[(2*kp  )*16 + u];
        uint4 o = Vf4[(2*kp+1)*16 + u];
        uint4 w0, w1;
        w0.x = __byte_perm(e.x, o.x, 0x5410);  w0.y = __byte_perm(e.x, o.x, 0x7632);
        w0.z = __byte_perm(e.y, o.y, 0x5410);  w0.w = __byte_perm(e.y, o.y, 0x7632);
        w1.x = __byte_perm(e.z, o.z, 0x5410);  w1.y = __byte_perm(e.z, o.z, 0x7632);
        w1.z = __byte_perm(e.w, o.w, 0x5410);  w1.w = __byte_perm(e.w, o.w, 0x7632);
        *(uint4*)&Vp[kp*136 + u*8    ] = w0;
        *(uint4*)&Vp[kp*136 + u*8 + 4] = w1;
    }
    __syncthreads();

    const int r0 = wrp * 16;
    const int ra = r0 + lg, rb = ra + 8;

    /* ================= S = Q K^T ====================================== */
    float s[16][4];
    #pragma unroll
    for (int n = 0; n < 16; n++) {
        s[n][0] = 0.f; s[n][1] = 0.f; s[n][2] = 0.f; s[n][3] = 0.f;
    }

    const uint4* Qg4 = g_q4 + (size_t)blockIdx.x * 4096 + (size_t)(r0 + lg)*4 + la;
    uint4 qa[2][2];
    qa[0][0] = Qg4[0];
    qa[0][1] = Qg4[32];

    #pragma unroll 1
    for (int kt = 0; kt < 8; kt++) {
        const int cur = kt & 1;
        if (kt < 7) {
            qa[cur^1][0] = Qg4[(kt+1)*512];
            qa[cur^1][1] = Qg4[(kt+1)*512 + 32];
        }
        const uint32_t ah0 = qa[cur][0].x, al0 = qa[cur][0].y;
        const uint32_t ah2 = qa[cur][0].z, al2 = qa[cur][0].w;
        const uint32_t ah1 = qa[cur][1].x, al1 = qa[cur][1].y;
        const uint32_t ah3 = qa[cur][1].z, al3 = qa[cur][1].w;

        const uint4* kb = &Ksm[kt*512 + lg*4 + la];
        #pragma unroll
        for (int n = 0; n < 16; n++) {
            uint4 Bf = kb[n*32];
            mma_bf16(s[n], ah0, ah1, ah2, ah3, Bf.x, Bf.z);
            mma_bf16(s[n], ah0, ah1, ah2, ah3, Bf.y, Bf.w);
            mma_bf16(s[n], al0, al1, al2, al3, Bf.x, Bf.z);
        }
    }

    /* ================= row softmax ==================================== */
    float ia, ib;
    {
        float ma = -1e30f, mb = -1e30f;
        #pragma unroll
        for (int n = 0; n < 16; n++) {
            ma = fmaxf(ma, fmaxf(s[n][0], s[n][1]));
            mb = fmaxf(mb, fmaxf(s[n][2], s[n][3]));
        }
        ma = fmaxf(ma, __shfl_xor_sync(0xffffffffu, ma, 1));
        ma = fmaxf(ma, __shfl_xor_sync(0xffffffffu, ma, 2));
        mb = fmaxf(mb, __shfl_xor_sync(0xffffffffu, mb, 1));
        mb = fmaxf(mb, __shfl_xor_sync(0xffffffffu, mb, 2));

        float sa = 0.f, sb = 0.f;
        #pragma unroll
        for (int n = 0; n < 16; n++) {
            s[n][0] = __expf(s[n][0] - ma);  sa += s[n][0];
            s[n][1] = __expf(s[n][1] - ma);  sa += s[n][1];
            s[n][2] = __expf(s[n][2] - mb);  sb += s[n][2];
            s[n][3] = __expf(s[n][3] - mb);  sb += s[n][3];
        }
        sa += __shfl_xor_sync(0xffffffffu, sa, 1);
        sa += __shfl_xor_sync(0xffffffffu, sa, 2);
        sb += __shfl_xor_sync(0xffffffffu, sb, 1);
        sb += __shfl_xor_sync(0xffffffffu, sb, 2);
        ia = 1.0f / sa;  ib = 1.0f / sb;
    }

    /* ================= O = A V : A built in registers ================= */
    /* S C-frag (thread lg,la) holds exactly the AV A-frag values:       */
    /* a0 = A[ra][kt16+2la..+1] = s[2kt][0,1]; a1 = A[rb][...] = s[2kt][2,3];
       a2 = s[2kt+1][0,1]; a3 = s[2kt+1][2,3].                           */
    float o[16][4];
    #pragma unroll
    for (int n = 0; n < 16; n++) {
        o[n][0] = 0.f; o[n][1] = 0.f; o[n][2] = 0.f; o[n][3] = 0.f;
    }

    #pragma unroll 1
    for (int kt = 0; kt < 8; kt++) {
        const uint32_t a0 = f16pack(s[2*kt  ][0]*ia, s[2*kt  ][1]*ia);
        const uint32_t a1 = f16pack(s[2*kt  ][2]*ib, s[2*kt  ][3]*ib);
        const uint32_t a2 = f16pack(s[2*kt+1][0]*ia, s[2*kt+1][1]*ia);
        const uint32_t a3 = f16pack(s[2*kt+1][2]*ib, s[2*kt+1][3]*ib);

        const int w0v = (kt*8 + la) * 136;
        #pragma unroll
        for (int n = 0; n < 16; n++) {
            uint32_t b0 = Vp[w0v + n*8 + lg];
            uint32_t b1 = Vp[w0v + 4*136 + n*8 + lg];
            mma_f16(o[n], a0, a1, a2, a3, b0, b1);
        }
    }

    /* ---- O direct to global as fp16 (u32 = 2 cols) ---- */
    #pragma unroll
    for (int n = 0; n < 16; n++) {
        *(uint32_t*)&g_of[base + (size_t)ra*128 + n*8 + 2*la] = f16pack(o[n][0], o[n][1]);
        *(uint32_t*)&g_of[base + (size_t)rb*128 + n*8 + 2*la] = f16pack(o[n][2], o[n][3]);
    }
}

/* ------------------------------------------------------------------ */
/* Phase 3: output projection, 2-MMA fp16 (W 2-term split, o fp16).    */
/* ------------------------------------------------------------------ */
#define OPP 264                            /* u32 pitch, 264%32=8 -> cf */
#define P3_SMEM (32 * OPP * 4)             /* 33792 B                   */

__global__ void __launch_bounds__(256, 2) proj_o_kernel(
    float* __restrict__ out,
    const float* __restrict__ wo, const float* __restrict__ bo)
{
    extern __shared__ uint32_t op[];       /* [32][264] fp16x2 ch-pairs */

    const int tid  = threadIdx.x;
    const int lane = tid & 31;
    const int wrp  = tid >> 5;
    const int lg   = lane >> 2;
    const int la   = lane & 3;
    const int s0   = blockIdx.x * 256;

    const int c0 = (wrp & 3) * 16;
    const int hf = wrp >> 2;

    uint32_t ah[16], al[16];
    #pragma unroll
    for (int kt = 0; kt < 4; kt++) {
        int kk = kt*16 + 2*la;
        float2 w0 = *(const float2*)&wo[(c0 + lg    )*64 + kk    ];
        float2 w1 = *(const float2*)&wo[(c0 + lg + 8)*64 + kk    ];
        float2 w2 = *(const float2*)&wo[(c0 + lg    )*64 + kk + 8];
        float2 w3 = *(const float2*)&wo[(c0 + lg + 8)*64 + kk + 8];
        f16_split2(w0.x, w0.y, ah[kt*4+0], al[kt*4+0]);
        f16_split2(w1.x, w1.y, ah[kt*4+1], al[kt*4+1]);
        f16_split2(w2.x, w2.y, ah[kt*4+2], al[kt*4+2]);
        f16_split2(w3.x, w3.y, ah[kt*4+3], al[kt*4+3]);
    }
    const float b1 = bo[c0 + lg];
    const float b2 = bo[c0 + lg + 8];

    /* ---- stage o: channel-pair packing via byte_perm (ALL 256 cols) ---- */
    for (int i = tid; i < 1024; i += 256) {
        int kp = i >> 5, u = i & 31;
        uint4 e = *(const uint4*)&g_of[(size_t)(2*kp  )*S_TOT + s0 + u*8];
        uint4 o = *(const uint4*)&g_of[(size_t)(2*kp+1)*S_TOT + s0 + u*8];
        uint4 w0, w1;
        w0.x = __byte_perm(e.x, o.x, 0x5410);  w0.y = __byte_perm(e.x, o.x, 0x7632);
        w0.z = __byte_perm(e.y, o.y, 0x5410);  w0.w = __byte_perm(e.y, o.y, 0x7632);
        w1.x = __byte_perm(e.z, o.z, 0x5410);  w1.y = __byte_perm(e.z, o.z, 0x7632);
        w1.z = __byte_perm(e.w, o.w, 0x5410);  w1.w = __byte_perm(e.w, o.w, 0x7632);
        *(uint4*)&op[kp*OPP + u*8    ] = w0;
        *(uint4*)&op[kp*OPP + u*8 + 4] = w1;
    }
    __syncthreads();

    #pragma unroll 1
    for (int qq = 0; qq < 2; qq++) {
        float c[8][4];
        #pragma unroll
        for (int n = 0; n < 8; n++) {
            c[n][0] = b1; c[n][1] = b1; c[n][2] = b2; c[n][3] = b2;
        }

        #pragma unroll 1
        for (int kt = 0; kt < 4; kt++) {
            const int w0i = (kt*8 + la)*OPP + hf*128 + qq*64 + lg;
            #pragma unroll
            for (int n = 0; n < 8; n++) {
                uint32_t B0 = op[w0i + n*8];
                uint32_t B1 = op[w0i + 4*OPP + n*8];
                mma_f16(c[n], ah[kt*4+0], ah[kt*4+1], ah[kt*4+2], ah[kt*4+3], B0, B1);
                mma_f16(c[n], al[kt*4+0], al[kt*4+1], al[kt*4+2], al[kt*4+3], B0, B1);
            }
        }

        #pragma unroll
        for (int n = 0; n < 8; n++) {
            size_t col = (size_t)(s0 + hf*128 + qq*64 + n*8 + 2*la);
            *(float2*)&out[(size_t)(c0 + lg    )*S_TOT + col] = make_float2(c[n][0], c[n][1]);
            *(float2*)&out[(size_t)(c0 + lg + 8)*S_TOT + col] = make_float2(c[n][2], c[n][3]);
        }
    }
}

/* ------------------------------------------------------------------ */
extern "C" void kernel_launch(void* const* d_in, const int* in_sizes, int n_in,
                              void* d_out, int out_size)
{
    const float* x  = (const float*)d_in[0];
    const float* wq = (const float*)d_in[1];
    const float* bq = (const float*)d_in[2];
    const float* wk = (const float*)d_in[3];
    const float* bk = (const float*)d_in[4];
    const float* wv = (const float*)d_in[5];
    const float* bv = (const float*)d_in[6];
    const float* wo = (const float*)d_in[7];
    const float* bo = (const float*)d_in[8];

    cudaFuncSetAttribute(qkv_kernel,    cudaFuncAttributeMaxDynamicSharedMemorySize, P1_SMEM);
    cudaFuncSetAttribute(attn_kernel,   cudaFuncAttributeMaxDynamicSharedMemorySize, AT_SMEM);
    cudaFuncSetAttribute(proj_o_kernel, cudaFuncAttributeMaxDynamicSharedMemorySize, P3_SMEM);

    qkv_kernel<<<S_TOT/256, 384, P1_SMEM>>>(x, wq, bq, wk, bk, wv, bv);
    attn_kernel<<<NSLAB, 256, AT_SMEM>>>();
    proj_o_kernel<<<S_TOT/256, 256, P3_SMEM>>>((float*)d_out, wo, bo);
}

// round 15
// speedup vs baseline: 1.1550x; 1.1550x over previous
#include <cuda_runtime.h>
#include <cuda_bf16.h>
#include <cuda_fp16.h>
#include <math.h>
#include <stdint.h>

#define CH    64
#define DDIM  48
#define WDIM  128
#define HDIM  128
#define S_TOT (DDIM*WDIM*HDIM)   /* 786432 spatial positions */
#define SLAB  (WDIM*HDIM)        /* 16384 per (c,d) slab     */
#define NSLAB (CH*DDIM)          /* 3072 attention problems  */

#define QSCALE 0.594603557501360533f   /* 8^(-1/4) */

/* q/k fragment-ordered uint4 {hi,lo,hi+4,lo+4}; v fp16x2 pairs; O fp16 */
__device__ uint4          g_q4[CH * S_TOT / 4];
__device__ uint4          g_k4[CH * S_TOT / 4];
__device__ uint32_t       g_vf[CH * S_TOT / 2];
__device__ unsigned short g_of[CH * S_TOT];

/* ---------------- mma.sync helpers (legal in compute_103 PTX) ---------- */
__device__ __forceinline__ void mma_bf16(float c[4],
                                         uint32_t a0, uint32_t a1, uint32_t a2, uint32_t a3,
                                         uint32_t b0, uint32_t b1) {
    asm volatile(
        "mma.sync.aligned.m16n8k16.row.col.f32.bf16.bf16.f32 "
        "{%0,%1,%2,%3}, {%4,%5,%6,%7}, {%8,%9}, {%0,%1,%2,%3};"
        : "+f"(c[0]), "+f"(c[1]), "+f"(c[2]), "+f"(c[3])
        : "r"(a0), "r"(a1), "r"(a2), "r"(a3), "r"(b0), "r"(b1));
}
__device__ __forceinline__ void mma_f16(float c[4],
                                        uint32_t a0, uint32_t a1, uint32_t a2, uint32_t a3,
                                        uint32_t b0, uint32_t b1) {
    asm volatile(
        "mma.sync.aligned.m16n8k16.row.col.f32.f16.f16.f32 "
        "{%0,%1,%2,%3}, {%4,%5,%6,%7}, {%8,%9}, {%0,%1,%2,%3};"
        : "+f"(c[0]), "+f"(c[1]), "+f"(c[2]), "+f"(c[3])
        : "r"(a0), "r"(a1), "r"(a2), "r"(a3), "r"(b0), "r"(b1));
}
/* 2-term bf16 Dekker split of a pair (x->low half, y->high half) */
__device__ __forceinline__ void bf16_split2(float x, float y, uint32_t& h, uint32_t& l) {
    __nv_bfloat162 hb = __floats2bfloat162_rn(x, y);
    float rx = x - __bfloat162float(hb.x);
    float ry = y - __bfloat162float(hb.y);
    __nv_bfloat162 lb = __floats2bfloat162_rn(rx, ry);
    h = *(uint32_t*)&hb;
    l = *(uint32_t*)&lb;
}
/* 2-term fp16 Dekker split of a pair */
__device__ __forceinline__ void f16_split2(float x, float y, uint32_t& h, uint32_t& l) {
    __half hx = __float2half_rn(x), hy = __float2half_rn(y);
    __half lx = __float2half_rn(x - __half2float(hx));
    __half ly = __float2half_rn(y - __half2float(hy));
    __half2 hh = __halves2half2(hx, hy);
    __half2 ll = __halves2half2(lx, ly);
    h = *(uint32_t*)&hh;
    l = *(uint32_t*)&ll;
}
__device__ __forceinline__ uint32_t f16pack(float x, float y) {
    __half2 h = __floats2half2_rn(x, y);
    return *(uint32_t*)&h;
}

/* ------------------------------------------------------------------ */
/* Phase 1: fused QKV projection, bf16 m16n8k16, 3-term split.         */
/* ------------------------------------------------------------------ */
#define XP2 268                           /* uint2 pitch (bank-checked) */
#define P1_SMEM (32 * XP2 * 8)            /* 68608 B                    */

__global__ void __launch_bounds__(384, 2) qkv_kernel(
    const float* __restrict__ x,
    const float* __restrict__ wq, const float* __restrict__ bq,
    const float* __restrict__ wk, const float* __restrict__ bk,
    const float* __restrict__ wv, const float* __restrict__ bv)
{
    extern __shared__ uint2 xs[];          /* [32][268] {hi,lo} */

    const int tid  = threadIdx.x;
    const int lane = tid & 31;
    const int wrp  = tid >> 5;
    const int lg   = lane >> 2;
    const int la   = lane & 3;
    const int s0   = blockIdx.x * 256;
    const int d    = s0 / 16384;
    const int wb   = (s0 % 16384) / 128;

    const int p  = wrp >> 2;                 /* 0=q 1=k 2=v */
    const int c0 = (wrp & 3) * 16;
    const float* W = (p == 0) ? wq : (p == 1) ? wk : wv;
    const float* B = (p == 0) ? bq : (p == 1) ? bk : bv;

    uint32_t ah[16], al[16];
    #pragma unroll
    for (int kt = 0; kt < 4; kt++) {
        int kk = kt*16 + 2*la;
        float2 w0 = *(const float2*)&W[(c0 + lg    )*64 + kk    ];
        float2 w1 = *(const float2*)&W[(c0 + lg + 8)*64 + kk    ];
        float2 w2 = *(const float2*)&W[(c0 + lg    )*64 + kk + 8];
        float2 w3 = *(const float2*)&W[(c0 + lg + 8)*64 + kk + 8];
        bf16_split2(w0.x, w0.y, ah[kt*4+0], al[kt*4+0]);
        bf16_split2(w1.x, w1.y, ah[kt*4+1], al[kt*4+1]);
        bf16_split2(w2.x, w2.y, ah[kt*4+2], al[kt*4+2]);
        bf16_split2(w3.x, w3.y, ah[kt*4+3], al[kt*4+3]);
    }
    const float b1 = B[c0 + lg];
    const float b2 = B[c0 + lg + 8];
    const float scale = (p == 0) ? QSCALE : 1.0f;
    uint4* g4 = (p == 0) ? g_q4 : g_k4;

    for (int i = tid; i < 32*64; i += 384) {
        int kp = i >> 6, q4 = i & 63;
        int col0 = q4 * 4;
        float4 a = *(const float4*)&x[(size_t)(2*kp  ) * S_TOT + s0 + col0];
        float4 b = *(const float4*)&x[(size_t)(2*kp+1) * S_TOT + s0 + col0];
        uint4 wh, wl;
        bf16_split2(a.x, b.x, wh.x, wl.x);
        bf16_split2(a.y, b.y, wh.y, wl.y);
        bf16_split2(a.z, b.z, wh.z, wl.z);
        bf16_split2(a.w, b.w, wh.w, wl.w);
        *(uint4*)&xs[kp*XP2 + col0    ] = make_uint4(wh.x, wl.x, wh.y, wl.y);
        *(uint4*)&xs[kp*XP2 + col0 + 2] = make_uint4(wh.z, wl.z, wh.w, wl.w);
    }
    __syncthreads();

    #pragma unroll 1
    for (int qt = 0; qt < 4; qt++) {
        float c[8][4];
        #pragma unroll
        for (int n = 0; n < 8; n++) {
            c[n][0] = b1; c[n][1] = b1; c[n][2] = b2; c[n][3] = b2;
        }

        #pragma unroll 1
        for (int kt = 0; kt < 4; kt++) {
            const int b0i = (8*kt + la)*XP2 + qt*64 + lg;
            const int b1i = b0i + 4*XP2;
            #pragma unroll
            for (int n = 0; n < 8; n++) {
                uint2 B0 = xs[b0i + n*8];
                uint2 B1 = xs[b1i + n*8];
                mma_bf16(c[n], ah[kt*4+0], ah[kt*4+1], ah[kt*4+2], ah[kt*4+3], B0.x, B1.x);
                mma_bf16(c[n], ah[kt*4+0], ah[kt*4+1], ah[kt*4+2], ah[kt*4+3], B0.y, B1.y);
                mma_bf16(c[n], al[kt*4+0], al[kt*4+1], al[kt*4+2], al[kt*4+3], B0.x, B1.x);
            }
        }

        if (p < 2) {
            const int w = wb + (qt >> 1);
            #pragma unroll
            for (int ne = 0; ne < 8; ne += 2) {
                const int kt_h = (qt & 1)*4 + (ne >> 1);
                const size_t fi = (size_t)d*4096 + kt_h*512 + w*4 + la;
                uint32_t h0, l0, h1, l1;
                bf16_split2(c[ne  ][0]*scale, c[ne  ][1]*scale, h0, l0);
                bf16_split2(c[ne+1][0]*scale, c[ne+1][1]*scale, h1, l1);
                g4[(size_t)(c0 + lg    )*(S_TOT/4) + fi] = make_uint4(h0, l0, h1, l1);
                bf16_split2(c[ne  ][2]*scale, c[ne  ][3]*scale, h0, l0);
                bf16_split2(c[ne+1][2]*scale, c[ne+1][3]*scale, h1, l1);
                g4[(size_t)(c0 + lg + 8)*(S_TOT/4) + fi] = make_uint4(h0, l0, h1, l1);
            }
        } else {
            #pragma unroll
            for (int n = 0; n < 8; n++) {
                const int scol = ((s0 + qt*64 + n*8) >> 1) + la;
                g_vf[(size_t)(c0 + lg    )*(S_TOT/2) + scol] = f16pack(c[n][0], c[n][1]);
                g_vf[(size_t)(c0 + lg + 8)*(S_TOT/2) + scol] = f16pack(c[n][2], c[n][3]);
            }
        }
    }
}

/* ------------------------------------------------------------------ */
/* Phase 2: attention. A kept in registers as packed fp16 a-frags      */
/* (32 regs, s dies at packing); AV n-loop split in two halves so      */
/* o is 32 regs/pass -> no spills under the 128-reg cap.               */
/* ------------------------------------------------------------------ */
#define ATV_OFF 65536
#define AT_SMEM (65536 + 34816)

__global__ void __launch_bounds__(256, 2) attn_kernel()
{
    extern __shared__ char smc[];
    uint4*    Ksm = (uint4*)smc;                  /* [8][128][4] uint4  */
    uint32_t* Vp  = (uint32_t*)(smc + ATV_OFF);   /* [64][136] fp16x2   */

    const int tid  = threadIdx.x;
    const int lane = tid & 31;
    const int wrp  = tid >> 5;
    const int lg   = lane >> 2;
    const int la   = lane & 3;
    const size_t base = (size_t)blockIdx.x * SLAB;

    const uint4* Kg4 = g_k4 + (size_t)blockIdx.x * 4096;
    for (int i = tid; i < 4096; i += 256)
        Ksm[i] = Kg4[i];
    const uint4* Vf4 = (const uint4*)g_vf + (size_t)blockIdx.x * 2048;
    for (int i = tid; i < 1024; i += 256) {
        int kp = i >> 4, u = i & 15;
        uint4 e = Vf4[(2*kp  )*16 + u];
        uint4 o = Vf4[(2*kp+1)*16 + u];
        uint4 w0, w1;
        w0.x = __byte_perm(e.x, o.x, 0x5410);  w0.y = __byte_perm(e.x, o.x, 0x7632);
        w0.z = __byte_perm(e.y, o.y, 0x5410);  w0.w = __byte_perm(e.y, o.y, 0x7632);
        w1.x = __byte_perm(e.z, o.z, 0x5410);  w1.y = __byte_perm(e.z, o.z, 0x7632);
        w1.z = __byte_perm(e.w, o.w, 0x5410);  w1.w = __byte_perm(e.w, o.w, 0x7632);
        *(uint4*)&Vp[kp*136 + u*8    ] = w0;
        *(uint4*)&Vp[kp*136 + u*8 + 4] = w1;
    }
    __syncthreads();

    const int r0 = wrp * 16;
    const int ra = r0 + lg, rb = ra + 8;

    /* ================= S = Q K^T ====================================== */
    float s[16][4];
    #pragma unroll
    for (int n = 0; n < 16; n++) {
        s[n][0] = 0.f; s[n][1] = 0.f; s[n][2] = 0.f; s[n][3] = 0.f;
    }

    const uint4* Qg4 = g_q4 + (size_t)blockIdx.x * 4096 + (size_t)(r0 + lg)*4 + la;
    uint4 qa[2][2];
    qa[0][0] = Qg4[0];
    qa[0][1] = Qg4[32];

    #pragma unroll 1
    for (int kt = 0; kt < 8; kt++) {
        const int cur = kt & 1;
        if (kt < 7) {
            qa[cur^1][0] = Qg4[(kt+1)*512];
            qa[cur^1][1] = Qg4[(kt+1)*512 + 32];
        }
        const uint32_t ah0 = qa[cur][0].x, al0 = qa[cur][0].y;
        const uint32_t ah2 = qa[cur][0].z, al2 = qa[cur][0].w;
        const uint32_t ah1 = qa[cur][1].x, al1 = qa[cur][1].y;
        const uint32_t ah3 = qa[cur][1].z, al3 = qa[cur][1].w;

        const uint4* kb = &Ksm[kt*512 + lg*4 + la];
        #pragma unroll
        for (int n = 0; n < 16; n++) {
            uint4 Bf = kb[n*32];
            mma_bf16(s[n], ah0, ah1, ah2, ah3, Bf.x, Bf.z);
            mma_bf16(s[n], ah0, ah1, ah2, ah3, Bf.y, Bf.w);
            mma_bf16(s[n], al0, al1, al2, al3, Bf.x, Bf.z);
        }
    }

    /* ================= row softmax ==================================== */
    float ia, ib;
    {
        float ma = -1e30f, mb = -1e30f;
        #pragma unroll
        for (int n = 0; n < 16; n++) {
            ma = fmaxf(ma, fmaxf(s[n][0], s[n][1]));
            mb = fmaxf(mb, fmaxf(s[n][2], s[n][3]));
        }
        ma = fmaxf(ma, __shfl_xor_sync(0xffffffffu, ma, 1));
        ma = fmaxf(ma, __shfl_xor_sync(0xffffffffu, ma, 2));
        mb = fmaxf(mb, __shfl_xor_sync(0xffffffffu, mb, 1));
        mb = fmaxf(mb, __shfl_xor_sync(0xffffffffu, mb, 2));

        float sa = 0.f, sb = 0.f;
        #pragma unroll
        for (int n = 0; n < 16; n++) {
            s[n][0] = __expf(s[n][0] - ma);  sa += s[n][0];
            s[n][1] = __expf(s[n][1] - ma);  sa += s[n][1];
            s[n][2] = __expf(s[n][2] - mb);  sb += s[n][2];
            s[n][3] = __expf(s[n][3] - mb);  sb += s[n][3];
        }
        sa += __shfl_xor_sync(0xffffffffu, sa, 1);
        sa += __shfl_xor_sync(0xffffffffu, sa, 2);
        sb += __shfl_xor_sync(0xffffffffu, sb, 1);
        sb += __shfl_xor_sync(0xffffffffu, sb, 2);
        ia = 1.0f / sa;  ib = 1.0f / sb;
    }

    /* ---- pack A fragments into registers; s dies here (32 u32 live) -- */
    uint32_t afr[32];
    #pragma unroll
    for (int kt = 0; kt < 8; kt++) {
        afr[kt*4+0] = f16pack(s[2*kt  ][0]*ia, s[2*kt  ][1]*ia);
        afr[kt*4+1] = f16pack(s[2*kt  ][2]*ib, s[2*kt  ][3]*ib);
        afr[kt*4+2] = f16pack(s[2*kt+1][0]*ia, s[2*kt+1][1]*ia);
        afr[kt*4+3] = f16pack(s[2*kt+1][2]*ib, s[2*kt+1][3]*ib);
    }

    /* ================= O = A V : two n-halves, o = 32 regs/pass ======= */
    #pragma unroll 1
    for (int half = 0; half < 2; half++) {
        float o[8][4];
        #pragma unroll
        for (int n = 0; n < 8; n++) {
            o[n][0] = 0.f; o[n][1] = 0.f; o[n][2] = 0.f; o[n][3] = 0.f;
        }

        #pragma unroll 1
        for (int kt = 0; kt < 8; kt++) {
            const int w0v = (kt*8 + la) * 136 + half*64;
            #pragma unroll
            for (int n = 0; n < 8; n++) {
                uint32_t b0 = Vp[w0v + n*8 + lg];
                uint32_t b1 = Vp[w0v + 4*136 + n*8 + lg];
                mma_f16(o[n], afr[kt*4+0], afr[kt*4+1], afr[kt*4+2], afr[kt*4+3], b0, b1);
            }
        }

        #pragma unroll
        for (int n = 0; n < 8; n++) {
            const int col = half*64 + n*8 + 2*la;
            *(uint32_t*)&g_of[base + (size_t)ra*128 + col] = f16pack(o[n][0], o[n][1]);
            *(uint32_t*)&g_of[base + (size_t)rb*128 + col] = f16pack(o[n][2], o[n][3]);
        }
    }
}

/* ------------------------------------------------------------------ */
/* Phase 3: output projection, 2-MMA fp16 (W 2-term split, o fp16).    */
/* ------------------------------------------------------------------ */
#define OPP 264                            /* u32 pitch, 264%32=8 -> cf */
#define P3_SMEM (32 * OPP * 4)             /* 33792 B                   */

__global__ void __launch_bounds__(256, 2) proj_o_kernel(
    float* __restrict__ out,
    const float* __restrict__ wo, const float* __restrict__ bo)
{
    extern __shared__ uint32_t op[];       /* [32][264] fp16x2 ch-pairs */

    const int tid  = threadIdx.x;
    const int lane = tid & 31;
    const int wrp  = tid >> 5;
    const int lg   = lane >> 2;
    const int la   = lane & 3;
    const int s0   = blockIdx.x * 256;

    const int c0 = (wrp & 3) * 16;
    const int hf = wrp >> 2;

    uint32_t ah[16], al[16];
    #pragma unroll
    for (int kt = 0; kt < 4; kt++) {
        int kk = kt*16 + 2*la;
        float2 w0 = *(const float2*)&wo[(c0 + lg    )*64 + kk    ];
        float2 w1 = *(const float2*)&wo[(c0 + lg + 8)*64 + kk    ];
        float2 w2 = *(const float2*)&wo[(c0 + lg    )*64 + kk + 8];
        float2 w3 = *(const float2*)&wo[(c0 + lg + 8)*64 + kk + 8];
        f16_split2(w0.x, w0.y, ah[kt*4+0], al[kt*4+0]);
        f16_split2(w1.x, w1.y, ah[kt*4+1], al[kt*4+1]);
        f16_split2(w2.x, w2.y, ah[kt*4+2], al[kt*4+2]);
        f16_split2(w3.x, w3.y, ah[kt*4+3], al[kt*4+3]);
    }
    const float b1 = bo[c0 + lg];
    const float b2 = bo[c0 + lg + 8];

    /* ---- stage o: channel-pair packing via byte_perm (ALL 256 cols) ---- */
    for (int i = tid; i < 1024; i += 256) {
        int kp = i >> 5, u = i & 31;
        uint4 e = *(const uint4*)&g_of[(size_t)(2*kp  )*S_TOT + s0 + u*8];
        uint4 o = *(const uint4*)&g_of[(size_t)(2*kp+1)*S_TOT + s0 + u*8];
        uint4 w0, w1;
        w0.x = __byte_perm(e.x, o.x, 0x5410);  w0.y = __byte_perm(e.x, o.x, 0x7632);
        w0.z = __byte_perm(e.y, o.y, 0x5410);  w0.w = __byte_perm(e.y, o.y, 0x7632);
        w1.x = __byte_perm(e.z, o.z, 0x5410);  w1.y = __byte_perm(e.z, o.z, 0x7632);
        w1.z = __byte_perm(e.w, o.w, 0x5410);  w1.w = __byte_perm(e.w, o.w, 0x7632);
        *(uint4*)&op[kp*OPP + u*8    ] = w0;
        *(uint4*)&op[kp*OPP + u*8 + 4] = w1;
    }
    __syncthreads();

    #pragma unroll 1
    for (int qq = 0; qq < 2; qq++) {
        float c[8][4];
        #pragma unroll
        for (int n = 0; n < 8; n++) {
            c[n][0] = b1; c[n][1] = b1; c[n][2] = b2; c[n][3] = b2;
        }

        #pragma unroll 1
        for (int kt = 0; kt < 4; kt++) {
            const int w0i = (kt*8 + la)*OPP + hf*128 + qq*64 + lg;
            #pragma unroll
            for (int n = 0; n < 8; n++) {
                uint32_t B0 = op[w0i + n*8];
                uint32_t B1 = op[w0i + 4*OPP + n*8];
                mma_f16(c[n], ah[kt*4+0], ah[kt*4+1], ah[kt*4+2], ah[kt*4+3], B0, B1);
                mma_f16(c[n], al[kt*4+0], al[kt*4+1], al[kt*4+2], al[kt*4+3], B0, B1);
            }
        }

        #pragma unroll
        for (int n = 0; n < 8; n++) {
            size_t col = (size_t)(s0 + hf*128 + qq*64 + n*8 + 2*la);
            *(float2*)&out[(size_t)(c0 + lg    )*S_TOT + col] = make_float2(c[n][0], c[n][1]);
            *(float2*)&out[(size_t)(c0 + lg + 8)*S_TOT + col] = make_float2(c[n][2], c[n][3]);
        }
    }
}

/* ------------------------------------------------------------------ */
extern "C" void kernel_launch(void* const* d_in, const int* in_sizes, int n_in,
                              void* d_out, int out_size)
{
    const float* x  = (const float*)d_in[0];
    const float* wq = (const float*)d_in[1];
    const float* bq = (const float*)d_in[2];
    const float* wk = (const float*)d_in[3];
    const float* bk = (const float*)d_in[4];
    const float* wv = (const float*)d_in[5];
    const float* bv = (const float*)d_in[6];
    const float* wo = (const float*)d_in[7];
    const float* bo = (const float*)d_in[8];

    cudaFuncSetAttribute(qkv_kernel,    cudaFuncAttributeMaxDynamicSharedMemorySize, P1_SMEM);
    cudaFuncSetAttribute(attn_kernel,   cudaFuncAttributeMaxDynamicSharedMemorySize, AT_SMEM);
    cudaFuncSetAttribute(proj_o_kernel, cudaFuncAttributeMaxDynamicSharedMemorySize, P3_SMEM);

    qkv_kernel<<<S_TOT/256, 384, P1_SMEM>>>(x, wq, bq, wk, bk, wv, bv);
    attn_kernel<<<NSLAB, 256, AT_SMEM>>>();
    proj_o_kernel<<<S_TOT/256, 256, P3_SMEM>>>((float*)d_out, wo, bo);
}

// round 16
// speedup vs baseline: 1.1632x; 1.0070x over previous
#include <cuda_runtime.h>
#include <cuda_bf16.h>
#include <cuda_fp16.h>
#include <math.h>
#include <stdint.h>

#define CH    64
#define DDIM  48
#define WDIM  128
#define HDIM  128
#define S_TOT (DDIM*WDIM*HDIM)   /* 786432 spatial positions */
#define SLAB  (WDIM*HDIM)        /* 16384 per (c,d) slab     */
#define NSLAB (CH*DDIM)          /* 3072 attention problems  */

#define QSCALE 0.594603557501360533f   /* 8^(-1/4) */

/* q/k fragment-ordered uint4 {hi,lo,hi+4,lo+4}; v fp16x2 pairs; O fp16 */
__device__ uint4          g_q4[CH * S_TOT / 4];
__device__ uint4          g_k4[CH * S_TOT / 4];
__device__ uint32_t       g_vf[CH * S_TOT / 2];
__device__ unsigned short g_of[CH * S_TOT];

/* ---------------- mma.sync helpers (legal in compute_103 PTX) ---------- */
__device__ __forceinline__ void mma_bf16(float c[4],
                                         uint32_t a0, uint32_t a1, uint32_t a2, uint32_t a3,
                                         uint32_t b0, uint32_t b1) {
    asm volatile(
        "mma.sync.aligned.m16n8k16.row.col.f32.bf16.bf16.f32 "
        "{%0,%1,%2,%3}, {%4,%5,%6,%7}, {%8,%9}, {%0,%1,%2,%3};"
        : "+f"(c[0]), "+f"(c[1]), "+f"(c[2]), "+f"(c[3])
        : "r"(a0), "r"(a1), "r"(a2), "r"(a3), "r"(b0), "r"(b1));
}
__device__ __forceinline__ void mma_f16(float c[4],
                                        uint32_t a0, uint32_t a1, uint32_t a2, uint32_t a3,
                                        uint32_t b0, uint32_t b1) {
    asm volatile(
        "mma.sync.aligned.m16n8k16.row.col.f32.f16.f16.f32 "
        "{%0,%1,%2,%3}, {%4,%5,%6,%7}, {%8,%9}, {%0,%1,%2,%3};"
        : "+f"(c[0]), "+f"(c[1]), "+f"(c[2]), "+f"(c[3])
        : "r"(a0), "r"(a1), "r"(a2), "r"(a3), "r"(b0), "r"(b1));
}
/* 2-term bf16 Dekker split of a pair (x->low half, y->high half) */
__device__ __forceinline__ void bf16_split2(float x, float y, uint32_t& h, uint32_t& l) {
    __nv_bfloat162 hb = __floats2bfloat162_rn(x, y);
    float rx = x - __bfloat162float(hb.x);
    float ry = y - __bfloat162float(hb.y);
    __nv_bfloat162 lb = __floats2bfloat162_rn(rx, ry);
    h = *(uint32_t*)&hb;
    l = *(uint32_t*)&lb;
}
/* 2-term fp16 Dekker split of a pair */
__device__ __forceinline__ void f16_split2(float x, float y, uint32_t& h, uint32_t& l) {
    __half hx = __float2half_rn(x), hy = __float2half_rn(y);
    __half lx = __float2half_rn(x - __half2float(hx));
    __half ly = __float2half_rn(y - __half2float(hy));
    __half2 hh = __halves2half2(hx, hy);
    __half2 ll = __halves2half2(lx, ly);
    h = *(uint32_t*)&hh;
    l = *(uint32_t*)&ll;
}
__device__ __forceinline__ uint32_t f16pack(float x, float y) {
    __half2 h = __floats2half2_rn(x, y);
    return *(uint32_t*)&h;
}

/* ------------------------------------------------------------------ */
/* Phase 1: fused QKV projection, bf16 m16n8k16, 3-term split.         */
/* ------------------------------------------------------------------ */
#define XP2 268                           /* uint2 pitch (bank-checked) */
#define P1_SMEM (32 * XP2 * 8)            /* 68608 B                    */

__global__ void __launch_bounds__(384, 2) qkv_kernel(
    const float* __restrict__ x,
    const float* __restrict__ wq, const float* __restrict__ bq,
    const float* __restrict__ wk, const float* __restrict__ bk,
    const float* __restrict__ wv, const float* __restrict__ bv)
{
    extern __shared__ uint2 xs[];          /* [32][268] {hi,lo} */

    const int tid  = threadIdx.x;
    const int lane = tid & 31;
    const int wrp  = tid >> 5;
    const int lg   = lane >> 2;
    const int la   = lane & 3;
    const int s0   = blockIdx.x * 256;
    const int d    = s0 / 16384;
    const int wb   = (s0 % 16384) / 128;

    const int p  = wrp >> 2;                 /* 0=q 1=k 2=v */
    const int c0 = (wrp & 3) * 16;
    const float* W = (p == 0) ? wq : (p == 1) ? wk : wv;
    const float* B = (p == 0) ? bq : (p == 1) ? bk : bv;

    uint32_t ah[16], al[16];
    #pragma unroll
    for (int kt = 0; kt < 4; kt++) {
        int kk = kt*16 + 2*la;
        float2 w0 = *(const float2*)&W[(c0 + lg    )*64 + kk    ];
        float2 w1 = *(const float2*)&W[(c0 + lg + 8)*64 + kk    ];
        float2 w2 = *(const float2*)&W[(c0 + lg    )*64 + kk + 8];
        float2 w3 = *(const float2*)&W[(c0 + lg + 8)*64 + kk + 8];
        bf16_split2(w0.x, w0.y, ah[kt*4+0], al[kt*4+0]);
        bf16_split2(w1.x, w1.y, ah[kt*4+1], al[kt*4+1]);
        bf16_split2(w2.x, w2.y, ah[kt*4+2], al[kt*4+2]);
        bf16_split2(w3.x, w3.y, ah[kt*4+3], al[kt*4+3]);
    }
    const float b1 = B[c0 + lg];
    const float b2 = B[c0 + lg + 8];
    const float scale = (p == 0) ? QSCALE : 1.0f;
    uint4* g4 = (p == 0) ? g_q4 : g_k4;

    for (int i = tid; i < 32*64; i += 384) {
        int kp = i >> 6, q4 = i & 63;
        int col0 = q4 * 4;
        float4 a = *(const float4*)&x[(size_t)(2*kp  ) * S_TOT + s0 + col0];
        float4 b = *(const float4*)&x[(size_t)(2*kp+1) * S_TOT + s0 + col0];
        uint4 wh, wl;
        bf16_split2(a.x, b.x, wh.x, wl.x);
        bf16_split2(a.y, b.y, wh.y, wl.y);
        bf16_split2(a.z, b.z, wh.z, wl.z);
        bf16_split2(a.w, b.w, wh.w, wl.w);
        *(uint4*)&xs[kp*XP2 + col0    ] = make_uint4(wh.x, wl.x, wh.y, wl.y);
        *(uint4*)&xs[kp*XP2 + col0 + 2] = make_uint4(wh.z, wl.z, wh.w, wl.w);
    }
    __syncthreads();

    #pragma unroll 1
    for (int qt = 0; qt < 4; qt++) {
        float c[8][4];
        #pragma unroll
        for (int n = 0; n < 8; n++) {
            c[n][0] = b1; c[n][1] = b1; c[n][2] = b2; c[n][3] = b2;
        }

        #pragma unroll 2
        for (int kt = 0; kt < 4; kt++) {
            const int b0i = (8*kt + la)*XP2 + qt*64 + lg;
            const int b1i = b0i + 4*XP2;
            #pragma unroll
            for (int n = 0; n < 8; n++) {
                uint2 B0 = xs[b0i + n*8];
                uint2 B1 = xs[b1i + n*8];
                mma_bf16(c[n], ah[kt*4+0], ah[kt*4+1], ah[kt*4+2], ah[kt*4+3], B0.x, B1.x);
                mma_bf16(c[n], ah[kt*4+0], ah[kt*4+1], ah[kt*4+2], ah[kt*4+3], B0.y, B1.y);
                mma_bf16(c[n], al[kt*4+0], al[kt*4+1], al[kt*4+2], al[kt*4+3], B0.x, B1.x);
            }
        }

        if (p < 2) {
            const int w = wb + (qt >> 1);
            #pragma unroll
            for (int ne = 0; ne < 8; ne += 2) {
                const int kt_h = (qt & 1)*4 + (ne >> 1);
                const size_t fi = (size_t)d*4096 + kt_h*512 + w*4 + la;
                uint32_t h0, l0, h1, l1;
                bf16_split2(c[ne  ][0]*scale, c[ne  ][1]*scale, h0, l0);
                bf16_split2(c[ne+1][0]*scale, c[ne+1][1]*scale, h1, l1);
                g4[(size_t)(c0 + lg    )*(S_TOT/4) + fi] = make_uint4(h0, l0, h1, l1);
                bf16_split2(c[ne  ][2]*scale, c[ne  ][3]*scale, h0, l0);
                bf16_split2(c[ne+1][2]*scale, c[ne+1][3]*scale, h1, l1);
                g4[(size_t)(c0 + lg + 8)*(S_TOT/4) + fi] = make_uint4(h0, l0, h1, l1);
            }
        } else {
            #pragma unroll
            for (int n = 0; n < 8; n++) {
                const int scol = ((s0 + qt*64 + n*8) >> 1) + la;
                g_vf[(size_t)(c0 + lg    )*(S_TOT/2) + scol] = f16pack(c[n][0], c[n][1]);
                g_vf[(size_t)(c0 + lg + 8)*(S_TOT/2) + scol] = f16pack(c[n][2], c[n][3]);
            }
        }
    }
}

/* ------------------------------------------------------------------ */
/* Phase 2: attention — R13 structure (Fa smem round-trip; proven).    */
/* ------------------------------------------------------------------ */
#define ATV_OFF 65536
#define AT_SMEM (65536 + 34816)

__global__ void __launch_bounds__(256, 2) attn_kernel()
{
    extern __shared__ char smc[];
    uint4*    Ksm = (uint4*)smc;                  /* [8][128][4] uint4  */
    uint2*    Fa  = (uint2*)smc;                  /* [8][128][4] uint2  */
    uint32_t* Vp  = (uint32_t*)(smc + ATV_OFF);   /* [64][136] fp16x2   */

    const int tid  = threadIdx.x;
    const int lane = tid & 31;
    const int wrp  = tid >> 5;
    const int lg   = lane >> 2;
    const int la   = lane & 3;
    const size_t base = (size_t)blockIdx.x * SLAB;

    const uint4* Kg4 = g_k4 + (size_t)blockIdx.x * 4096;
    for (int i = tid; i < 4096; i += 256)
        Ksm[i] = Kg4[i];
    const uint4* Vf4 = (const uint4*)g_vf + (size_t)blockIdx.x * 2048;
    for (int i = tid; i < 1024; i += 256) {
        int kp = i >> 4, u = i & 15;
        uint4 e = Vf4[(2*kp  )*16 + u];
        uint4 o = Vf4[(2*kp+1)*16 + u];
        uint4 w0, w1;
        w0.x = __byte_perm(e.x, o.x, 0x5410);  w0.y = __byte_perm(e.x, o.x, 0x7632);
        w0.z = __byte_perm(e.y, o.y, 0x5410);  w0.w = __byte_perm(e.y, o.y, 0x7632);
        w1.x = __byte_perm(e.z, o.z, 0x5410);  w1.y = __byte_perm(e.z, o.z, 0x7632);
        w1.z = __byte_perm(e.w, o.w, 0x5410);  w1.w = __byte_perm(e.w, o.w, 0x7632);
        *(uint4*)&Vp[kp*136 + u*8    ] = w0;
        *(uint4*)&Vp[kp*136 + u*8 + 4] = w1;
    }
    __syncthreads();

    const int r0 = wrp * 16;
    const int ra = r0 + lg, rb = ra + 8;

    /* ================= S = Q K^T ====================================== */
    float s[16][4];
    #pragma unroll
    for (int n = 0; n < 16; n++) {
        s[n][0] = 0.f; s[n][1] = 0.f; s[n][2] = 0.f; s[n][3] = 0.f;
    }

    const uint4* Qg4 = g_q4 + (size_t)blockIdx.x * 4096 + (size_t)(r0 + lg)*4 + la;
    uint4 qa[2][2];
    qa[0][0] = Qg4[0];
    qa[0][1] = Qg4[32];

    #pragma unroll 1
    for (int kt = 0; kt < 8; kt++) {
        const int cur = kt & 1;
        if (kt < 7) {
            qa[cur^1][0] = Qg4[(kt+1)*512];
            qa[cur^1][1] = Qg4[(kt+1)*512 + 32];
        }
        const uint32_t ah0 = qa[cur][0].x, al0 = qa[cur][0].y;
        const uint32_t ah2 = qa[cur][0].z, al2 = qa[cur][0].w;
        const uint32_t ah1 = qa[cur][1].x, al1 = qa[cur][1].y;
        const uint32_t ah3 = qa[cur][1].z, al3 = qa[cur][1].w;

        const uint4* kb = &Ksm[kt*512 + lg*4 + la];
        #pragma unroll
        for (int n = 0; n < 16; n++) {
            uint4 Bf = kb[n*32];
            mma_bf16(s[n], ah0, ah1, ah2, ah3, Bf.x, Bf.z);
            mma_bf16(s[n], ah0, ah1, ah2, ah3, Bf.y, Bf.w);
            mma_bf16(s[n], al0, al1, al2, al3, Bf.x, Bf.z);
        }
    }

    /* ================= row softmax ==================================== */
    float ia, ib;
    {
        float ma = -1e30f, mb = -1e30f;
        #pragma unroll
        for (int n = 0; n < 16; n++) {
            ma = fmaxf(ma, fmaxf(s[n][0], s[n][1]));
            mb = fmaxf(mb, fmaxf(s[n][2], s[n][3]));
        }
        ma = fmaxf(ma, __shfl_xor_sync(0xffffffffu, ma, 1));
        ma = fmaxf(ma, __shfl_xor_sync(0xffffffffu, ma, 2));
        mb = fmaxf(mb, __shfl_xor_sync(0xffffffffu, mb, 1));
        mb = fmaxf(mb, __shfl_xor_sync(0xffffffffu, mb, 2));

        float sa = 0.f, sb = 0.f;
        #pragma unroll
        for (int n = 0; n < 16; n++) {
            s[n][0] = __expf(s[n][0] - ma);  sa += s[n][0];
            s[n][1] = __expf(s[n][1] - ma);  sa += s[n][1];
            s[n][2] = __expf(s[n][2] - mb);  sb += s[n][2];
            s[n][3] = __expf(s[n][3] - mb);  sb += s[n][3];
        }
        sa += __shfl_xor_sync(0xffffffffu, sa, 1);
        sa += __shfl_xor_sync(0xffffffffu, sa, 2);
        sb += __shfl_xor_sync(0xffffffffu, sb, 1);
        sb += __shfl_xor_sync(0xffffffffu, sb, 2);
        ia = 1.0f / sa;  ib = 1.0f / sb;
    }

    /* all warps done reading K before A overlays it */
    __syncthreads();
    #pragma unroll
    for (int kt = 0; kt < 8; kt++) {
        Fa[kt*512 + ra*4 + la] =
            make_uint2(f16pack(s[2*kt  ][0]*ia, s[2*kt  ][1]*ia),
                       f16pack(s[2*kt+1][0]*ia, s[2*kt+1][1]*ia));
        Fa[kt*512 + rb*4 + la] =
            make_uint2(f16pack(s[2*kt  ][2]*ib, s[2*kt  ][3]*ib),
                       f16pack(s[2*kt+1][2]*ib, s[2*kt+1][3]*ib));
    }
    __syncwarp();

    /* ================= O = A V ======================================== */
    float o[16][4];
    #pragma unroll
    for (int n = 0; n < 16; n++) {
        o[n][0] = 0.f; o[n][1] = 0.f; o[n][2] = 0.f; o[n][3] = 0.f;
    }

    #pragma unroll 1
    for (int kt = 0; kt < 8; kt++) {
        uint2 u2a = Fa[kt*512 + (r0 + lg    )*4 + la];
        uint2 u2b = Fa[kt*512 + (r0 + lg + 8)*4 + la];
        const uint32_t a0 = u2a.x, a2 = u2a.y;
        const uint32_t a1 = u2b.x, a3 = u2b.y;

        const int w0v = (kt*8 + la) * 136;
        #pragma unroll
        for (int n = 0; n < 16; n++) {
            uint32_t b0 = Vp[w0v + n*8 + lg];
            uint32_t b1 = Vp[w0v + 4*136 + n*8 + lg];
            mma_f16(o[n], a0, a1, a2, a3, b0, b1);
        }
    }

    /* ---- O direct to global as fp16 (u32 = 2 cols) ---- */
    #pragma unroll
    for (int n = 0; n < 16; n++) {
        *(uint32_t*)&g_of[base + (size_t)ra*128 + n*8 + 2*la] = f16pack(o[n][0], o[n][1]);
        *(uint32_t*)&g_of[base + (size_t)rb*128 + n*8 + 2*la] = f16pack(o[n][2], o[n][3]);
    }
}

/* ------------------------------------------------------------------ */
/* Phase 3: output projection, 2-MMA fp16 (W 2-term split, o fp16).    */
/* ------------------------------------------------------------------ */
#define OPP 264                            /* u32 pitch, 264%32=8 -> cf */
#define P3_SMEM (32 * OPP * 4)             /* 33792 B                   */

__global__ void __launch_bounds__(256, 2) proj_o_kernel(
    float* __restrict__ out,
    const float* __restrict__ wo, const float* __restrict__ bo)
{
    extern __shared__ uint32_t op[];       /* [32][264] fp16x2 ch-pairs */

    const int tid  = threadIdx.x;
    const int lane = tid & 31;
    const int wrp  = tid >> 5;
    const int lg   = lane >> 2;
    const int la   = lane & 3;
    const int s0   = blockIdx.x * 256;

    const int c0 = (wrp & 3) * 16;
    const int hf = wrp >> 2;

    uint32_t ah[16], al[16];
    #pragma unroll
    for (int kt = 0; kt < 4; kt++) {
        int kk = kt*16 + 2*la;
        float2 w0 = *(const float2*)&wo[(c0 + lg    )*64 + kk    ];
        float2 w1 = *(const float2*)&wo[(c0 + lg + 8)*64 + kk    ];
        float2 w2 = *(const float2*)&wo[(c0 + lg    )*64 + kk + 8];
        float2 w3 = *(const float2*)&wo[(c0 + lg + 8)*64 + kk + 8];
        f16_split2(w0.x, w0.y, ah[kt*4+0], al[kt*4+0]);
        f16_split2(w1.x, w1.y, ah[kt*4+1], al[kt*4+1]);
        f16_split2(w2.x, w2.y, ah[kt*4+2], al[kt*4+2]);
        f16_split2(w3.x, w3.y, ah[kt*4+3], al[kt*4+3]);
    }
    const float b1 = bo[c0 + lg];
    const float b2 = bo[c0 + lg + 8];

    /* ---- stage o: channel-pair packing via byte_perm (ALL 256 cols) ---- */
    for (int i = tid; i < 1024; i += 256) {
        int kp = i >> 5, u = i & 31;
        uint4 e = *(const uint4*)&g_of[(size_t)(2*kp  )*S_TOT + s0 + u*8];
        uint4 o = *(const uint4*)&g_of[(size_t)(2*kp+1)*S_TOT + s0 + u*8];
        uint4 w0, w1;
        w0.x = __byte_perm(e.x, o.x, 0x5410);  w0.y = __byte_perm(e.x, o.x, 0x7632);
        w0.z = __byte_perm(e.y, o.y, 0x5410);  w0.w = __byte_perm(e.y, o.y, 0x7632);
        w1.x = __byte_perm(e.z, o.z, 0x5410);  w1.y = __byte_perm(e.z, o.z, 0x7632);
        w1.z = __byte_perm(e.w, o.w, 0x5410);  w1.w = __byte_perm(e.w, o.w, 0x7632);
        *(uint4*)&op[kp*OPP + u*8    ] = w0;
        *(uint4*)&op[kp*OPP + u*8 + 4] = w1;
    }
    __syncthreads();

    #pragma unroll 1
    for (int qq = 0; qq < 2; qq++) {
        float c[8][4];
        #pragma unroll
        for (int n = 0; n < 8; n++) {
            c[n][0] = b1; c[n][1] = b1; c[n][2] = b2; c[n][3] = b2;
        }

        #pragma unroll 2
        for (int kt = 0; kt < 4; kt++) {
            const int w0i = (kt*8 + la)*OPP + hf*128 + qq*64 + lg;
            #pragma unroll
            for (int n = 0; n < 8; n++) {
                uint32_t B0 = op[w0i + n*8];
                uint32_t B1 = op[w0i + 4*OPP + n*8];
                mma_f16(c[n], ah[kt*4+0], ah[kt*4+1], ah[kt*4+2], ah[kt*4+3], B0, B1);
                mma_f16(c[n], al[kt*4+0], al[kt*4+1], al[kt*4+2], al[kt*4+3], B0, B1);
            }
        }

        #pragma unroll
        for (int n = 0; n < 8; n++) {
            size_t col = (size_t)(s0 + hf*128 + qq*64 + n*8 + 2*la);
            *(float2*)&out[(size_t)(c0 + lg    )*S_TOT + col] = make_float2(c[n][0], c[n][1]);
            *(float2*)&out[(size_t)(c0 + lg + 8)*S_TOT + col] = make_float2(c[n][2], c[n][3]);
        }
    }
}

/* ------------------------------------------------------------------ */
extern "C" void kernel_launch(void* const* d_in, const int* in_sizes, int n_in,
                              void* d_out, int out_size)
{
    const float* x  = (const float*)d_in[0];
    const float* wq = (const float*)d_in[1];
    const float* bq = (const float*)d_in[2];
    const float* wk = (const float*)d_in[3];
    const float* bk = (const float*)d_in[4];
    const float* wv = (const float*)d_in[5];
    const float* bv = (const float*)d_in[6];
    const float* wo = (const float*)d_in[7];
    const float* bo = (const float*)d_in[8];

    cudaFuncSetAttribute(qkv_kernel,    cudaFuncAttributeMaxDynamicSharedMemorySize, P1_SMEM);
    cudaFuncSetAttribute(attn_kernel,   cudaFuncAttributeMaxDynamicSharedMemorySize, AT_SMEM);
    cudaFuncSetAttribute(proj_o_kernel, cudaFuncAttributeMaxDynamicSharedMemorySize, P3_SMEM);

    qkv_kernel<<<S_TOT/256, 384, P1_SMEM>>>(x, wq, bq, wk, bk, wv, bv);
    attn_kernel<<<NSLAB, 256, AT_SMEM>>>();
    proj_o_kernel<<<S_TOT/256, 256, P3_SMEM>>>((float*)d_out, wo, bo);
}

// round 17
// speedup vs baseline: 1.1870x; 1.0205x over previous
#include <cuda_runtime.h>
#include <cuda_bf16.h>
#include <cuda_fp16.h>
#include <math.h>
#include <stdint.h>

#define CH    64
#define DDIM  48
#define WDIM  128
#define HDIM  128
#define S_TOT (DDIM*WDIM*HDIM)   /* 786432 spatial positions */
#define SLAB  (WDIM*HDIM)        /* 16384 per (c,d) slab     */
#define NSLAB (CH*DDIM)          /* 3072 attention problems  */

#define QSCALE 0.594603557501360533f   /* 8^(-1/4) */

/* q/k fragment-ordered uint4 {hi,lo,hi+4,lo+4}; v fp16x2 pairs; O fp16 */
__device__ uint4          g_q4[CH * S_TOT / 4];
__device__ uint4          g_k4[CH * S_TOT / 4];
__device__ uint32_t       g_vf[CH * S_TOT / 2];
__device__ unsigned short g_of[CH * S_TOT];

/* ---------------- mma.sync helpers (legal in compute_103 PTX) ---------- */
__device__ __forceinline__ void mma_bf16(float c[4],
                                         uint32_t a0, uint32_t a1, uint32_t a2, uint32_t a3,
                                         uint32_t b0, uint32_t b1) {
    asm volatile(
        "mma.sync.aligned.m16n8k16.row.col.f32.bf16.bf16.f32 "
        "{%0,%1,%2,%3}, {%4,%5,%6,%7}, {%8,%9}, {%0,%1,%2,%3};"
        : "+f"(c[0]), "+f"(c[1]), "+f"(c[2]), "+f"(c[3])
        : "r"(a0), "r"(a1), "r"(a2), "r"(a3), "r"(b0), "r"(b1));
}
__device__ __forceinline__ void mma_f16(float c[4],
                                        uint32_t a0, uint32_t a1, uint32_t a2, uint32_t a3,
                                        uint32_t b0, uint32_t b1) {
    asm volatile(
        "mma.sync.aligned.m16n8k16.row.col.f32.f16.f16.f32 "
        "{%0,%1,%2,%3}, {%4,%5,%6,%7}, {%8,%9}, {%0,%1,%2,%3};"
        : "+f"(c[0]), "+f"(c[1]), "+f"(c[2]), "+f"(c[3])
        : "r"(a0), "r"(a1), "r"(a2), "r"(a3), "r"(b0), "r"(b1));
}
/* 2-term bf16 Dekker split of a pair (x->low half, y->high half) */
__device__ __forceinline__ void bf16_split2(float x, float y, uint32_t& h, uint32_t& l) {
    __nv_bfloat162 hb = __floats2bfloat162_rn(x, y);
    float rx = x - __bfloat162float(hb.x);
    float ry = y - __bfloat162float(hb.y);
    __nv_bfloat162 lb = __floats2bfloat162_rn(rx, ry);
    h = *(uint32_t*)&hb;
    l = *(uint32_t*)&lb;
}
/* 2-term fp16 Dekker split of a pair */
__device__ __forceinline__ void f16_split2(float x, float y, uint32_t& h, uint32_t& l) {
    __half hx = __float2half_rn(x), hy = __float2half_rn(y);
    __half lx = __float2half_rn(x - __half2float(hx));
    __half ly = __float2half_rn(y - __half2float(hy));
    __half2 hh = __halves2half2(hx, hy);
    __half2 ll = __halves2half2(lx, ly);
    h = *(uint32_t*)&hh;
    l = *(uint32_t*)&ll;
}
__device__ __forceinline__ uint32_t f16pack(float x, float y) {
    __half2 h = __floats2half2_rn(x, y);
    return *(uint32_t*)&h;
}

/* ------------------------------------------------------------------ */
/* Phase 1: fused QKV projection, bf16 m16n8k16, 3-term split.         */
/* kt loop unroll 2 (measured win in R16).                             */
/* ------------------------------------------------------------------ */
#define XP2 268                           /* uint2 pitch (bank-checked) */
#define P1_SMEM (32 * XP2 * 8)            /* 68608 B                    */

__global__ void __launch_bounds__(384, 2) qkv_kernel(
    const float* __restrict__ x,
    const float* __restrict__ wq, const float* __restrict__ bq,
    const float* __restrict__ wk, const float* __restrict__ bk,
    const float* __restrict__ wv, const float* __restrict__ bv)
{
    extern __shared__ uint2 xs[];          /* [32][268] {hi,lo} */

    const int tid  = threadIdx.x;
    const int lane = tid & 31;
    const int wrp  = tid >> 5;
    const int lg   = lane >> 2;
    const int la   = lane & 3;
    const int s0   = blockIdx.x * 256;
    const int d    = s0 / 16384;
    const int wb   = (s0 % 16384) / 128;

    const int p  = wrp >> 2;                 /* 0=q 1=k 2=v */
    const int c0 = (wrp & 3) * 16;
    const float* W = (p == 0) ? wq : (p == 1) ? wk : wv;
    const float* B = (p == 0) ? bq : (p == 1) ? bk : bv;

    uint32_t ah[16], al[16];
    #pragma unroll
    for (int kt = 0; kt < 4; kt++) {
        int kk = kt*16 + 2*la;
        float2 w0 = *(const float2*)&W[(c0 + lg    )*64 + kk    ];
        float2 w1 = *(const float2*)&W[(c0 + lg + 8)*64 + kk    ];
        float2 w2 = *(const float2*)&W[(c0 + lg    )*64 + kk + 8];
        float2 w3 = *(const float2*)&W[(c0 + lg + 8)*64 + kk + 8];
        bf16_split2(w0.x, w0.y, ah[kt*4+0], al[kt*4+0]);
        bf16_split2(w1.x, w1.y, ah[kt*4+1], al[kt*4+1]);
        bf16_split2(w2.x, w2.y, ah[kt*4+2], al[kt*4+2]);
        bf16_split2(w3.x, w3.y, ah[kt*4+3], al[kt*4+3]);
    }
    const float b1 = B[c0 + lg];
    const float b2 = B[c0 + lg + 8];
    const float scale = (p == 0) ? QSCALE : 1.0f;
    uint4* g4 = (p == 0) ? g_q4 : g_k4;

    for (int i = tid; i < 32*64; i += 384) {
        int kp = i >> 6, q4 = i & 63;
        int col0 = q4 * 4;
        float4 a = *(const float4*)&x[(size_t)(2*kp  ) * S_TOT + s0 + col0];
        float4 b = *(const float4*)&x[(size_t)(2*kp+1) * S_TOT + s0 + col0];
        uint4 wh, wl;
        bf16_split2(a.x, b.x, wh.x, wl.x);
        bf16_split2(a.y, b.y, wh.y, wl.y);
        bf16_split2(a.z, b.z, wh.z, wl.z);
        bf16_split2(a.w, b.w, wh.w, wl.w);
        *(uint4*)&xs[kp*XP2 + col0    ] = make_uint4(wh.x, wl.x, wh.y, wl.y);
        *(uint4*)&xs[kp*XP2 + col0 + 2] = make_uint4(wh.z, wl.z, wh.w, wl.w);
    }
    __syncthreads();

    #pragma unroll 1
    for (int qt = 0; qt < 4; qt++) {
        float c[8][4];
        #pragma unroll
        for (int n = 0; n < 8; n++) {
            c[n][0] = b1; c[n][1] = b1; c[n][2] = b2; c[n][3] = b2;
        }

        #pragma unroll 2
        for (int kt = 0; kt < 4; kt++) {
            const int b0i = (8*kt + la)*XP2 + qt*64 + lg;
            const int b1i = b0i + 4*XP2;
            #pragma unroll
            for (int n = 0; n < 8; n++) {
                uint2 B0 = xs[b0i + n*8];
                uint2 B1 = xs[b1i + n*8];
                mma_bf16(c[n], ah[kt*4+0], ah[kt*4+1], ah[kt*4+2], ah[kt*4+3], B0.x, B1.x);
                mma_bf16(c[n], ah[kt*4+0], ah[kt*4+1], ah[kt*4+2], ah[kt*4+3], B0.y, B1.y);
                mma_bf16(c[n], al[kt*4+0], al[kt*4+1], al[kt*4+2], al[kt*4+3], B0.x, B1.x);
            }
        }

        if (p < 2) {
            const int w = wb + (qt >> 1);
            #pragma unroll
            for (int ne = 0; ne < 8; ne += 2) {
                const int kt_h = (qt & 1)*4 + (ne >> 1);
                const size_t fi = (size_t)d*4096 + kt_h*512 + w*4 + la;
                uint32_t h0, l0, h1, l1;
                bf16_split2(c[ne  ][0]*scale, c[ne  ][1]*scale, h0, l0);
                bf16_split2(c[ne+1][0]*scale, c[ne+1][1]*scale, h1, l1);
                g4[(size_t)(c0 + lg    )*(S_TOT/4) + fi] = make_uint4(h0, l0, h1, l1);
                bf16_split2(c[ne  ][2]*scale, c[ne  ][3]*scale, h0, l0);
                bf16_split2(c[ne+1][2]*scale, c[ne+1][3]*scale, h1, l1);
                g4[(size_t)(c0 + lg + 8)*(S_TOT/4) + fi] = make_uint4(h0, l0, h1, l1);
            }
        } else {
            #pragma unroll
            for (int n = 0; n < 8; n++) {
                const int scol = ((s0 + qt*64 + n*8) >> 1) + la;
                g_vf[(size_t)(c0 + lg    )*(S_TOT/2) + scol] = f16pack(c[n][0], c[n][1]);
                g_vf[(size_t)(c0 + lg + 8)*(S_TOT/2) + scol] = f16pack(c[n][2], c[n][3]);
            }
        }
    }
}

/* ------------------------------------------------------------------ */
/* Phase 2: attention — R13 structure verbatim (proven 637us config).  */
/* ------------------------------------------------------------------ */
#define ATV_OFF 65536
#define AT_SMEM (65536 + 34816)

__global__ void __launch_bounds__(256, 2) attn_kernel()
{
    extern __shared__ char smc[];
    uint4*    Ksm = (uint4*)smc;                  /* [8][128][4] uint4  */
    uint2*    Fa  = (uint2*)smc;                  /* [8][128][4] uint2  */
    uint32_t* Vp  = (uint32_t*)(smc + ATV_OFF);   /* [64][136] fp16x2   */

    const int tid  = threadIdx.x;
    const int lane = tid & 31;
    const int wrp  = tid >> 5;
    const int lg   = lane >> 2;
    const int la   = lane & 3;
    const size_t base = (size_t)blockIdx.x * SLAB;

    const uint4* Kg4 = g_k4 + (size_t)blockIdx.x * 4096;
    for (int i = tid; i < 4096; i += 256)
        Ksm[i] = Kg4[i];
    const uint4* Vf4 = (const uint4*)g_vf + (size_t)blockIdx.x * 2048;
    for (int i = tid; i < 1024; i += 256) {
        int kp = i >> 4, u = i & 15;
        uint4 e = Vf4[(2*kp  )*16 + u];
        uint4 o = Vf4[(2*kp+1)*16 + u];
        uint4 w0, w1;
        w0.x = __byte_perm(e.x, o.x, 0x5410);  w0.y = __byte_perm(e.x, o.x, 0x7632);
        w0.z = __byte_perm(e.y, o.y, 0x5410);  w0.w = __byte_perm(e.y, o.y, 0x7632);
        w1.x = __byte_perm(e.z, o.z, 0x5410);  w1.y = __byte_perm(e.z, o.z, 0x7632);
        w1.z = __byte_perm(e.w, o.w, 0x5410);  w1.w = __byte_perm(e.w, o.w, 0x7632);
        *(uint4*)&Vp[kp*136 + u*8    ] = w0;
        *(uint4*)&Vp[kp*136 + u*8 + 4] = w1;
    }
    __syncthreads();

    const int r0 = wrp * 16;
    const int ra = r0 + lg, rb = ra + 8;

    /* ================= S = Q K^T ====================================== */
    float s[16][4];
    #pragma unroll
    for (int n = 0; n < 16; n++) {
        s[n][0] = 0.f; s[n][1] = 0.f; s[n][2] = 0.f; s[n][3] = 0.f;
    }

    const uint4* Qg4 = g_q4 + (size_t)blockIdx.x * 4096 + (size_t)(r0 + lg)*4 + la;
    uint4 qa[2][2];
    qa[0][0] = Qg4[0];
    qa[0][1] = Qg4[32];

    #pragma unroll 1
    for (int kt = 0; kt < 8; kt++) {
        const int cur = kt & 1;
        if (kt < 7) {
            qa[cur^1][0] = Qg4[(kt+1)*512];
            qa[cur^1][1] = Qg4[(kt+1)*512 + 32];
        }
        const uint32_t ah0 = qa[cur][0].x, al0 = qa[cur][0].y;
        const uint32_t ah2 = qa[cur][0].z, al2 = qa[cur][0].w;
        const uint32_t ah1 = qa[cur][1].x, al1 = qa[cur][1].y;
        const uint32_t ah3 = qa[cur][1].z, al3 = qa[cur][1].w;

        const uint4* kb = &Ksm[kt*512 + lg*4 + la];
        #pragma unroll
        for (int n = 0; n < 16; n++) {
            uint4 Bf = kb[n*32];
            mma_bf16(s[n], ah0, ah1, ah2, ah3, Bf.x, Bf.z);
            mma_bf16(s[n], ah0, ah1, ah2, ah3, Bf.y, Bf.w);
            mma_bf16(s[n], al0, al1, al2, al3, Bf.x, Bf.z);
        }
    }

    /* ================= row softmax ==================================== */
    float ia, ib;
    {
        float ma = -1e30f, mb = -1e30f;
        #pragma unroll
        for (int n = 0; n < 16; n++) {
            ma = fmaxf(ma, fmaxf(s[n][0], s[n][1]));
            mb = fmaxf(mb, fmaxf(s[n][2], s[n][3]));
        }
        ma = fmaxf(ma, __shfl_xor_sync(0xffffffffu, ma, 1));
        ma = fmaxf(ma, __shfl_xor_sync(0xffffffffu, ma, 2));
        mb = fmaxf(mb, __shfl_xor_sync(0xffffffffu, mb, 1));
        mb = fmaxf(mb, __shfl_xor_sync(0xffffffffu, mb, 2));

        float sa = 0.f, sb = 0.f;
        #pragma unroll
        for (int n = 0; n < 16; n++) {
            s[n][0] = __expf(s[n][0] - ma);  sa += s[n][0];
            s[n][1] = __expf(s[n][1] - ma);  sa += s[n][1];
            s[n][2] = __expf(s[n][2] - mb);  sb += s[n][2];
            s[n][3] = __expf(s[n][3] - mb);  sb += s[n][3];
        }
        sa += __shfl_xor_sync(0xffffffffu, sa, 1);
        sa += __shfl_xor_sync(0xffffffffu, sa, 2);
        sb += __shfl_xor_sync(0xffffffffu, sb, 1);
        sb += __shfl_xor_sync(0xffffffffu, sb, 2);
        ia = 1.0f / sa;  ib = 1.0f / sb;
    }

    /* all warps done reading K before A overlays it */
    __syncthreads();
    #pragma unroll
    for (int kt = 0; kt < 8; kt++) {
        Fa[kt*512 + ra*4 + la] =
            make_uint2(f16pack(s[2*kt  ][0]*ia, s[2*kt  ][1]*ia),
                       f16pack(s[2*kt+1][0]*ia, s[2*kt+1][1]*ia));
        Fa[kt*512 + rb*4 + la] =
            make_uint2(f16pack(s[2*kt  ][2]*ib, s[2*kt  ][3]*ib),
                       f16pack(s[2*kt+1][2]*ib, s[2*kt+1][3]*ib));
    }
    __syncwarp();

    /* ================= O = A V ======================================== */
    float o[16][4];
    #pragma unroll
    for (int n = 0; n < 16; n++) {
        o[n][0] = 0.f; o[n][1] = 0.f; o[n][2] = 0.f; o[n][3] = 0.f;
    }

    #pragma unroll 1
    for (int kt = 0; kt < 8; kt++) {
        uint2 u2a = Fa[kt*512 + (r0 + lg    )*4 + la];
        uint2 u2b = Fa[kt*512 + (r0 + lg + 8)*4 + la];
        const uint32_t a0 = u2a.x, a2 = u2a.y;
        const uint32_t a1 = u2b.x, a3 = u2b.y;

        const int w0v = (kt*8 + la) * 136;
        #pragma unroll
        for (int n = 0; n < 16; n++) {
            uint32_t b0 = Vp[w0v + n*8 + lg];
            uint32_t b1 = Vp[w0v + 4*136 + n*8 + lg];
            mma_f16(o[n], a0, a1, a2, a3, b0, b1);
        }
    }

    /* ---- O direct to global as fp16 (u32 = 2 cols) ---- */
    #pragma unroll
    for (int n = 0; n < 16; n++) {
        *(uint32_t*)&g_of[base + (size_t)ra*128 + n*8 + 2*la] = f16pack(o[n][0], o[n][1]);
        *(uint32_t*)&g_of[base + (size_t)rb*128 + n*8 + 2*la] = f16pack(o[n][2], o[n][3]);
    }
}

/* ------------------------------------------------------------------ */
/* Phase 3: output projection, 2-MMA fp16 — R13 structure (unroll 1).  */
/* ------------------------------------------------------------------ */
#define OPP 264                            /* u32 pitch, 264%32=8 -> cf */
#define P3_SMEM (32 * OPP * 4)             /* 33792 B                   */

__global__ void __launch_bounds__(256, 2) proj_o_kernel(
    float* __restrict__ out,
    const float* __restrict__ wo, const float* __restrict__ bo)
{
    extern __shared__ uint32_t op[];       /* [32][264] fp16x2 ch-pairs */

    const int tid  = threadIdx.x;
    const int lane = tid & 31;
    const int wrp  = tid >> 5;
    const int lg   = lane >> 2;
    const int la   = lane & 3;
    const int s0   = blockIdx.x * 256;

    const int c0 = (wrp & 3) * 16;
    const int hf = wrp >> 2;

    uint32_t ah[16], al[16];
    #pragma unroll
    for (int kt = 0; kt < 4; kt++) {
        int kk = kt*16 + 2*la;
        float2 w0 = *(const float2*)&wo[(c0 + lg    )*64 + kk    ];
        float2 w1 = *(const float2*)&wo[(c0 + lg + 8)*64 + kk    ];
        float2 w2 = *(const float2*)&wo[(c0 + lg    )*64 + kk + 8];
        float2 w3 = *(const float2*)&wo[(c0 + lg + 8)*64 + kk + 8];
        f16_split2(w0.x, w0.y, ah[kt*4+0], al[kt*4+0]);
        f16_split2(w1.x, w1.y, ah[kt*4+1], al[kt*4+1]);
        f16_split2(w2.x, w2.y, ah[kt*4+2], al[kt*4+2]);
        f16_split2(w3.x, w3.y, ah[kt*4+3], al[kt*4+3]);
    }
    const float b1 = bo[c0 + lg];
    const float b2 = bo[c0 + lg + 8];

    /* ---- stage o: channel-pair packing via byte_perm (ALL 256 cols) ---- */
    for (int i = tid; i < 1024; i += 256) {
        int kp = i >> 5, u = i & 31;
        uint4 e = *(const uint4*)&g_of[(size_t)(2*kp  )*S_TOT + s0 + u*8];
        uint4 o = *(const uint4*)&g_of[(size_t)(2*kp+1)*S_TOT + s0 + u*8];
        uint4 w0, w1;
        w0.x = __byte_perm(e.x, o.x, 0x5410);  w0.y = __byte_perm(e.x, o.x, 0x7632);
        w0.z = __byte_perm(e.y, o.y, 0x5410);  w0.w = __byte_perm(e.y, o.y, 0x7632);
        w1.x = __byte_perm(e.z, o.z, 0x5410);  w1.y = __byte_perm(e.z, o.z, 0x7632);
        w1.z = __byte_perm(e.w, o.w, 0x5410);  w1.w = __byte_perm(e.w, o.w, 0x7632);
        *(uint4*)&op[kp*OPP + u*8    ] = w0;
        *(uint4*)&op[kp*OPP + u*8 + 4] = w1;
    }
    __syncthreads();

    #pragma unroll 1
    for (int qq = 0; qq < 2; qq++) {
        float c[8][4];
        #pragma unroll
        for (int n = 0; n < 8; n++) {
            c[n][0] = b1; c[n][1] = b1; c[n][2] = b2; c[n][3] = b2;
        }

        #pragma unroll 1
        for (int kt = 0; kt < 4; kt++) {
            const int w0i = (kt*8 + la)*OPP + hf*128 + qq*64 + lg;
            #pragma unroll
            for (int n = 0; n < 8; n++) {
                uint32_t B0 = op[w0i + n*8];
                uint32_t B1 = op[w0i + 4*OPP + n*8];
                mma_f16(c[n], ah[kt*4+0], ah[kt*4+1], ah[kt*4+2], ah[kt*4+3], B0, B1);
                mma_f16(c[n], al[kt*4+0], al[kt*4+1], al[kt*4+2], al[kt*4+3], B0, B1);
            }
        }

        #pragma unroll
        for (int n = 0; n < 8; n++) {
            size_t col = (size_t)(s0 + hf*128 + qq*64 + n*8 + 2*la);
            *(float2*)&out[(size_t)(c0 + lg    )*S_TOT + col] = make_float2(c[n][0], c[n][1]);
            *(float2*)&out[(size_t)(c0 + lg + 8)*S_TOT + col] = make_float2(c[n][2], c[n][3]);
        }
    }
}

/* ------------------------------------------------------------------ */
extern "C" void kernel_launch(void* const* d_in, const int* in_sizes, int n_in,
                              void* d_out, int out_size)
{
    const float* x  = (const float*)d_in[0];
    const float* wq = (const float*)d_in[1];
    const float* bq = (const float*)d_in[2];
    const float* wk = (const float*)d_in[3];
    const float* bk = (const float*)d_in[4];
    const float* wv = (const float*)d_in[5];
    const float* bv = (const float*)d_in[6];
    const float* wo = (const float*)d_in[7];
    const float* bo = (const float*)d_in[8];

    cudaFuncSetAttribute(qkv_kernel,    cudaFuncAttributeMaxDynamicSharedMemorySize, P1_SMEM);
    cudaFuncSetAttribute(attn_kernel,   cudaFuncAttributeMaxDynamicSharedMemorySize, AT_SMEM);
    cudaFuncSetAttribute(proj_o_kernel, cudaFuncAttributeMaxDynamicSharedMemorySize, P3_SMEM);

    qkv_kernel<<<S_TOT/256, 384, P1_SMEM>>>(x, wq, bq, wk, bk, wv, bv);
    attn_kernel<<<NSLAB, 256, AT_SMEM>>>();
    proj_o_kernel<<<S_TOT/256, 256, P3_SMEM>>>((float*)d_out, wo, bo);
}